// round 9
// baseline (speedup 1.0000x reference)
#include <cuda_runtime.h>
#include <cstddef>

// ---------------------------------------------------------------------------
// Collapsed model (only pyramid level L-1 survives the reference):
//   g[b,f]    = (1/256) * sum over 16x16 patch grid of x   (f = c*256+pi*16+pj)
//   root[b,d] = sum_f W_emb[d,f]*g[b,f] + b_emb[d] + pos4[d]
//   out[b,o]  = sum_d W_cls[o,d]*root[b,d] + b_cls[o]
//
// k1: pooling (R1 version, best measured 11.17us — at the DRAM ceiling).
// kB: root + logits fused, one software grid barrier (nanosleep poll).
// ---------------------------------------------------------------------------

#define NBB 128   // blocks in kB

__device__ float g_scratch[64 * 768];      // [b][768]
__device__ float root_scratch[64 * 128];
__device__ unsigned int kb_cnt, kb_reset;  // zero-initialized
__device__ volatile unsigned int kb_flag;

// ---- packed f32x2 helpers (sm_103a) ---------------------------------------
__device__ __forceinline__ unsigned long long pack2(float a, float b) {
    unsigned long long r;
    asm("mov.b64 %0, {%1, %2};" : "=l"(r) : "f"(a), "f"(b));
    return r;
}
__device__ __forceinline__ unsigned long long addf32x2(unsigned long long a,
                                                       unsigned long long b) {
    unsigned long long r;
    asm("add.rn.f32x2 %0, %1, %2;" : "=l"(r) : "l"(a), "l"(b));
    return r;
}
__device__ __forceinline__ void unpack2(unsigned long long p, float& a, float& b) {
    asm("mov.b64 {%0, %1}, %2;" : "=f"(a), "=f"(b) : "l"(p));
}
__device__ __forceinline__ float dot4(float4 a, float4 b) {
    return a.x * b.x + a.y * b.y + a.z * b.z + a.w * b.w;
}

// ---------------------------------------------------------------------------
// Kernel 1 (R1 version, best measured): strided pooling of x.
// grid (4 row-phases, 3 channels, 64 batch), 256 threads.
// ---------------------------------------------------------------------------
__global__ __launch_bounds__(256) void k1_pool(const float* __restrict__ x) {
    const int q = blockIdx.x;    // 0..3 row phase
    const int c = blockIdx.y;    // 0..2 channel
    const int b = blockIdx.z;    // 0..63 batch
    const int t = threadIdx.x;
    const int rbase = t >> 6;    // 0..3
    const int c4 = t & 63;       // float4 column 0..63
    const int pi = q * 4 + rbase;

    const float4* plane =
        reinterpret_cast<const float4*>(x + ((size_t)(b * 3 + c) << 16));

    float4 acc = make_float4(0.f, 0.f, 0.f, 0.f);
#pragma unroll
    for (int m = 0; m < 16; m++) {
        float4 v = plane[(pi + 16 * m) * 64 + c4];
        acc.x += v.x; acc.y += v.y; acc.z += v.z; acc.w += v.w;
    }

    __shared__ float4 s[4][64];
    s[rbase][c4] = acc;
    __syncthreads();

    if (t < 16) {
        const int rb = t >> 2;   // 0..3
        const int qq = t & 3;    // pj quad 0..3
        float4 sum = make_float4(0.f, 0.f, 0.f, 0.f);
#pragma unroll
        for (int j = 0; j < 16; j++) {
            float4 v = s[rb][qq + 4 * j];
            sum.x += v.x; sum.y += v.y; sum.z += v.z; sum.w += v.w;
        }
        const float sc = 1.0f / 256.0f;
        const int pi2 = q * 4 + rb;
        float4* gout = reinterpret_cast<float4*>(
            g_scratch + b * 768 + c * 256 + pi2 * 16 + qq * 4);
        *gout = make_float4(sum.x * sc, sum.y * sc, sum.z * sc, sum.w * sc);
    }
}

// ---------------------------------------------------------------------------
// Kernel B: fused root + logits, 128 blocks x 256 threads.
// Phase A: block (dt=bb&7, bt=bb>>3): 16 d's x 4 batches of root.
//          g[4][768] staged in smem; warp w does d = dt*16 + w*2 + dd.
// Barrier: single-line counter, releases via flag, pollers nanosleep.
// Phase B: block (ot=bb>>3, bt=bb&7): 63 o's x 8 batches of logits.
// ---------------------------------------------------------------------------
__global__ __launch_bounds__(256) void kB(
    const float* __restrict__ W_emb, const float* __restrict__ b_emb,
    const float* __restrict__ pos4, const float* __restrict__ W_cls,
    const float* __restrict__ b_cls, float* __restrict__ out) {
    const int bb = blockIdx.x;
    const int t = threadIdx.x;
    const int w = t >> 5;
    const int lane = t & 31;

    __shared__ float4 gs[4][192];   // 12 KB

    // ===================== Phase A: root ===================================
    {
        const int dt = bb & 7;
        const int bt = bb >> 3;

        // Stage g[bt*4 .. +3][768] (768 float4, coalesced from L2).
        const float4* gsrc =
            reinterpret_cast<const float4*>(g_scratch + bt * 4 * 768);
#pragma unroll
        for (int s = 0; s < 3; s++) {
            const int idx = t + 256 * s;          // 0..767
            gs[idx / 192][idx % 192] = __ldcg(gsrc + idx);
        }
        __syncthreads();

#pragma unroll
        for (int dd = 0; dd < 2; dd++) {
            const int d = dt * 16 + w * 2 + dd;
            const float4* wp =
                reinterpret_cast<const float4*>(W_emb + d * 768) + lane;
            float4 w4[6];
#pragma unroll
            for (int i = 0; i < 6; i++) w4[i] = __ldg(wp + 32 * i);

            float a0 = 0.f, a1 = 0.f, a2 = 0.f, a3 = 0.f;
#pragma unroll
            for (int i = 0; i < 6; i++) {
                const int idx = lane + 32 * i;
                a0 += dot4(w4[i], gs[0][idx]);
                a1 += dot4(w4[i], gs[1][idx]);
                a2 += dot4(w4[i], gs[2][idx]);
                a3 += dot4(w4[i], gs[3][idx]);
            }
            unsigned long long p01 = pack2(a0, a1);
            unsigned long long p23 = pack2(a2, a3);
#pragma unroll
            for (int off = 16; off >= 1; off >>= 1) {
                p01 = addf32x2(p01, __shfl_xor_sync(0xffffffffu, p01, off));
                p23 = addf32x2(p23, __shfl_xor_sync(0xffffffffu, p23, off));
            }
            if (lane == 0) {
                unpack2(p01, a0, a1);
                unpack2(p23, a2, a3);
                const float bias = b_emb[d] + pos4[d];
                root_scratch[(bt * 4 + 0) * 128 + d] = a0 + bias;
                root_scratch[(bt * 4 + 1) * 128 + d] = a1 + bias;
                root_scratch[(bt * 4 + 2) * 128 + d] = a2 + bias;
                root_scratch[(bt * 4 + 3) * 128 + d] = a3 + bias;
            }
        }
    }

    // ===================== Grid barrier (nanosleep poll) ===================
    __syncthreads();
    if (t == 0) {
        __threadfence();
        if (atomicAdd(&kb_cnt, 1u) == NBB - 1u) {
            kb_flag = 1u;
            __threadfence();
        } else {
            while (kb_flag == 0u) __nanosleep(64);
        }
    }
    __syncthreads();

    // ===================== Phase B: logits =================================
    {
        const int ot = bb >> 3;      // 0..15
        const int bt = bb & 7;       // 0..7

        float4 r4[8];
#pragma unroll
        for (int j = 0; j < 8; j++)
            r4[j] = __ldcg(reinterpret_cast<const float4*>(
                               root_scratch + (bt * 8 + j) * 128) + lane);

#pragma unroll
        for (int oo = 0; oo < 8; oo++) {
            const int k = w * 8 + oo;             // 0..63
            const int o = ot * 63 + k;
            if (k < 63 && o < 1000) {
                const float4 wv =
                    __ldg(reinterpret_cast<const float4*>(W_cls + o * 128) + lane);
                float acc[8];
#pragma unroll
                for (int j = 0; j < 8; j++) acc[j] = dot4(wv, r4[j]);

                unsigned long long p[4];
#pragma unroll
                for (int j = 0; j < 4; j++)
                    p[j] = pack2(acc[2 * j], acc[2 * j + 1]);
#pragma unroll
                for (int off = 16; off >= 1; off >>= 1) {
#pragma unroll
                    for (int j = 0; j < 4; j++)
                        p[j] = addf32x2(p[j],
                                        __shfl_xor_sync(0xffffffffu, p[j], off));
                }
                if (lane == 0) {
                    const float bc = b_cls[o];
#pragma unroll
                    for (int j = 0; j < 4; j++) {
                        float e0, e1;
                        unpack2(p[j], e0, e1);
                        out[(bt * 8 + 2 * j + 0) * 1000 + o] = e0 + bc;
                        out[(bt * 8 + 2 * j + 1) * 1000 + o] = e1 + bc;
                    }
                }
            }
        }
    }

    // ===================== Reset barrier state for next replay =============
    if (t == 0) {
        if (atomicAdd(&kb_reset, 1u) == NBB - 1u) {
            kb_cnt = 0u;
            kb_flag = 0u;
            __threadfence();
            kb_reset = 0u;
        }
    }
}

// ---------------------------------------------------------------------------
// Inputs (metadata order): 0:x 1:W_emb 2:b_emb 3:pos0 4:pos1 5:pos2 6:pos3
//                          7:pos4 8:W_cls 9:b_cls.  Output: (64,1000) f32.
// ---------------------------------------------------------------------------
extern "C" void kernel_launch(void* const* d_in, const int* in_sizes, int n_in,
                              void* d_out, int out_size) {
    const float* x     = (const float*)d_in[0];
    const float* W_emb = (const float*)d_in[1];
    const float* b_emb = (const float*)d_in[2];
    const float* pos4  = (const float*)d_in[7];
    const float* W_cls = (const float*)d_in[8];
    const float* b_cls = (const float*)d_in[9];
    float* out = (float*)d_out;

    k1_pool<<<dim3(4, 3, 64), 256>>>(x);
    kB<<<NBB, 256>>>(W_emb, b_emb, pos4, W_cls, b_cls, out);
}

// round 10
// speedup vs baseline: 1.3655x; 1.3655x over previous
#include <cuda_runtime.h>
#include <cstddef>

// ---------------------------------------------------------------------------
// Collapsed model (only pyramid level L-1 survives the reference):
//   g[b,f]    = (1/256) * sum over 16x16 patch grid of x   (f = c*256+pi*16+pj)
//   root[b,d] = sum_f W_emb[d,f]*g[b,f] + b_emb[d] + pos4[d]
//   out[b,o]  = sum_d W_cls[o,d]*root[b,d] + b_cls[o]
//
// k1 fuses pooling + the W_emb GEMM (fma pipe is idle during the DRAM sweep):
// block (q,c,b) owns the contiguous 64-wide f-slice fbase = c*256+q*64,
// stages the 128x64 W_emb tile in shared, and writes a deterministic partial
// root contribution root_part[q*3+c][b][0..127].  NO barriers, NO atomics.
// k3 stages the 12-way partial sum COALESCED into smem (the R2 failure was
// doing this scattered in registers), adds biases, then runs the proven
// warp-level logits GEMM.
// ---------------------------------------------------------------------------

__device__ float root_part[12 * 64 * 128];   // [p=(q*3+c)][b][d], 393 KB

// ---- packed f32x2 helpers (sm_103a) ---------------------------------------
__device__ __forceinline__ unsigned long long pack2(float a, float b) {
    unsigned long long r;
    asm("mov.b64 %0, {%1, %2};" : "=l"(r) : "f"(a), "f"(b));
    return r;
}
__device__ __forceinline__ unsigned long long addf32x2(unsigned long long a,
                                                       unsigned long long b) {
    unsigned long long r;
    asm("add.rn.f32x2 %0, %1, %2;" : "=l"(r) : "l"(a), "l"(b));
    return r;
}
__device__ __forceinline__ void unpack2(unsigned long long p, float& a, float& b) {
    asm("mov.b64 {%0, %1}, %2;" : "=f"(a), "=f"(b) : "l"(p));
}
__device__ __forceinline__ float dot4(float4 a, float4 b) {
    return a.x * b.x + a.y * b.y + a.z * b.z + a.w * b.w;
}

// ---------------------------------------------------------------------------
// Kernel 1: pooling + partial embedding (R2 version, verified correct).
// grid (4 row-phases, 3 channels, 64 batch), 256 threads.
// ---------------------------------------------------------------------------
__global__ __launch_bounds__(256, 5) void k1_pool_emb(
    const float* __restrict__ x, const float* __restrict__ W_emb) {
    const int q = blockIdx.x;    // 0..3 row phase
    const int c = blockIdx.y;    // 0..2 channel
    const int b = blockIdx.z;    // 0..63 batch
    const int t = threadIdx.x;
    const int rbase = t >> 6;    // 0..3
    const int c4 = t & 63;       // float4 column
    const int pi = q * 4 + rbase;

    const float4* plane =
        reinterpret_cast<const float4*>(x + ((size_t)(b * 3 + c) << 16));

    float4 acc = make_float4(0.f, 0.f, 0.f, 0.f);
#pragma unroll
    for (int m = 0; m < 16; m++) {
        float4 v = plane[(pi + 16 * m) * 64 + c4];
        acc.x += v.x; acc.y += v.y; acc.z += v.z; acc.w += v.w;
    }

    __shared__ float4 s[4][64];          // column partials
    __shared__ float wsh[128 * 65];      // W_emb tile, padded stride
    __shared__ float g_sh[64];           // this block's g slice
    __shared__ float ps[256];            // half-combine

    s[rbase][c4] = acc;

    // Stage W_emb tile: rows d=0..127, cols fbase..fbase+63.
    const int fbase = c * 256 + q * 64;
#pragma unroll
    for (int i = 0; i < 8; i++) {
        int idx4 = t + 256 * i;          // 0..2047 float4 slots
        int d = idx4 >> 4;               // 0..127
        int fq = idx4 & 15;              // float4 within row
        float4 w = *reinterpret_cast<const float4*>(W_emb + d * 768 + fbase + fq * 4);
        float* dst = &wsh[d * 65 + fq * 4];
        dst[0] = w.x; dst[1] = w.y; dst[2] = w.z; dst[3] = w.w;
    }
    __syncthreads();

    if (t < 16) {
        const int rb = t >> 2;
        const int qq = t & 3;
        float4 sum = make_float4(0.f, 0.f, 0.f, 0.f);
#pragma unroll
        for (int j = 0; j < 16; j++) {
            float4 v = s[rb][qq + 4 * j];
            sum.x += v.x; sum.y += v.y; sum.z += v.z; sum.w += v.w;
        }
        const float sc = 1.0f / 256.0f;
        const int fo = rb * 16 + qq * 4;
        g_sh[fo + 0] = sum.x * sc;
        g_sh[fo + 1] = sum.y * sc;
        g_sh[fo + 2] = sum.z * sc;
        g_sh[fo + 3] = sum.w * sc;
    }
    __syncthreads();

    // Partial root: thread (d = t&127, half = t>>7) does 32 FMAs.
    {
        const int d = t & 127;
        const int half = t >> 7;
        const float* wrow = &wsh[d * 65 + half * 32];
        const float* gp = &g_sh[half * 32];
        float acc2 = 0.f;
#pragma unroll
        for (int j = 0; j < 32; j++) acc2 += wrow[j] * gp[j];
        ps[t] = acc2;
    }
    __syncthreads();
    if (t < 128) {
        root_part[((q * 3 + c) * 64 + b) * 128 + t] = ps[t] + ps[t + 128];
    }
}

// ---------------------------------------------------------------------------
// Kernel 3: coalesced 12-partial reduce -> smem root -> logits.
// grid (16 o-tiles, 16 b-tiles) = 256 blocks, 256 threads (8 warps).
// Stage: thread t<128 (j=t>>5 batch, d4=t&31) sums 12 float4 partials
//        (each warp-load = 512B contiguous) + bias -> root4[j][d4].
// Logits: warp w handles o = ot*64 + w*8 + oo for 4 batches; two passes of
//        4 o's with packed f32x2 butterfly reductions.
// ---------------------------------------------------------------------------
__global__ __launch_bounds__(256) void k3_logits(
    const float* __restrict__ W_cls, const float* __restrict__ b_cls,
    const float* __restrict__ b_emb, const float* __restrict__ pos4,
    float* __restrict__ out) {
    const int ot = blockIdx.x;   // 0..15 -> o base ot*64
    const int bt = blockIdx.y;   // 0..15 -> batches bt*4..+3
    const int t = threadIdx.x;
    const int w = t >> 5;
    const int lane = t & 31;

    __shared__ float4 root4[4][32];

    if (t < 128) {
        const int j = t >> 5;    // batch within tile
        const int d4 = t & 31;   // float4 index over d
        const float4 be = reinterpret_cast<const float4*>(b_emb)[d4];
        const float4 pv = reinterpret_cast<const float4*>(pos4)[d4];
        float4 acc = make_float4(be.x + pv.x, be.y + pv.y,
                                 be.z + pv.z, be.w + pv.w);
        const float4* rp = reinterpret_cast<const float4*>(root_part);
#pragma unroll
        for (int p = 0; p < 12; p++) {
            float4 v = rp[(p * 64 + bt * 4 + j) * 32 + d4];
            acc.x += v.x; acc.y += v.y; acc.z += v.z; acc.w += v.w;
        }
        root4[j][d4] = acc;
    }
    __syncthreads();

    const float4 r0 = root4[0][lane];
    const float4 r1 = root4[1][lane];
    const float4 r2 = root4[2][lane];
    const float4 r3 = root4[3][lane];

#pragma unroll
    for (int pass = 0; pass < 2; pass++) {
        unsigned long long p01[4], p23[4];
        int obase = ot * 64 + w * 8 + pass * 4;
#pragma unroll
        for (int oo = 0; oo < 4; oo++) {
            const int o = obase + oo;
            float4 wv = make_float4(0.f, 0.f, 0.f, 0.f);
            if (o < 1000)
                wv = reinterpret_cast<const float4*>(W_cls)[o * 32 + lane];
            p01[oo] = pack2(dot4(wv, r0), dot4(wv, r1));
            p23[oo] = pack2(dot4(wv, r2), dot4(wv, r3));
        }
#pragma unroll
        for (int off = 16; off >= 1; off >>= 1) {
#pragma unroll
            for (int oo = 0; oo < 4; oo++) {
                p01[oo] = addf32x2(p01[oo], __shfl_xor_sync(0xffffffffu, p01[oo], off));
                p23[oo] = addf32x2(p23[oo], __shfl_xor_sync(0xffffffffu, p23[oo], off));
            }
        }
        if (lane == 0) {
#pragma unroll
            for (int oo = 0; oo < 4; oo++) {
                const int o = obase + oo;
                if (o < 1000) {
                    const float bc = b_cls[o];
                    float e0, e1, e2, e3;
                    unpack2(p01[oo], e0, e1);
                    unpack2(p23[oo], e2, e3);
                    out[(bt * 4 + 0) * 1000 + o] = e0 + bc;
                    out[(bt * 4 + 1) * 1000 + o] = e1 + bc;
                    out[(bt * 4 + 2) * 1000 + o] = e2 + bc;
                    out[(bt * 4 + 3) * 1000 + o] = e3 + bc;
                }
            }
        }
    }
}

// ---------------------------------------------------------------------------
// Inputs (metadata order): 0:x 1:W_emb 2:b_emb 3:pos0 4:pos1 5:pos2 6:pos3
//                          7:pos4 8:W_cls 9:b_cls.  Output: (64,1000) f32.
// ---------------------------------------------------------------------------
extern "C" void kernel_launch(void* const* d_in, const int* in_sizes, int n_in,
                              void* d_out, int out_size) {
    const float* x     = (const float*)d_in[0];
    const float* W_emb = (const float*)d_in[1];
    const float* b_emb = (const float*)d_in[2];
    const float* pos4  = (const float*)d_in[7];
    const float* W_cls = (const float*)d_in[8];
    const float* b_cls = (const float*)d_in[9];
    float* out = (float*)d_out;

    k1_pool_emb<<<dim3(4, 3, 64), 256>>>(x, W_emb);
    k3_logits<<<dim3(16, 16), 256>>>(W_cls, b_cls, b_emb, pos4, out);
}